// round 9
// baseline (speedup 1.0000x reference)
#include <cuda_runtime.h>

#define VOCAB   101
#define EMB     32
#define HID     32
#define T_STEPS 512
#define NWARP   8   // warps per block; grid = 148 blocks -> 1184 warps

// Precomputed per-token gate contributions: tbl[v][j] = (i, f, g, o)
__device__ float4 g_tbl[VOCAB * HID];
// Packed recurrence weights (f32x2 across k):
// g_wpk[(gate*16 + k2)*32 + j] = ( Wh[2*k2][gate*32+j], Wh[2*k2+1][gate*32+j] )
__device__ unsigned long long g_wpk[4 * 16 * 32];

__device__ __forceinline__ unsigned long long pack2(float lo, float hi) {
    unsigned long long r;
    asm("mov.b64 %0, {%1, %2};" : "=l"(r) : "f"(lo), "f"(hi));
    return r;
}
__device__ __forceinline__ float lo2(unsigned long long v) {
    return __uint_as_float((unsigned int)v);
}
__device__ __forceinline__ float hi2(unsigned long long v) {
    return __uint_as_float((unsigned int)(v >> 32));
}
// Packed double-rate fp32 FMA (Blackwell FFMA2)
__device__ __forceinline__ unsigned long long ffma2(unsigned long long a,
                                                    unsigned long long b,
                                                    unsigned long long c) {
    unsigned long long d;
    asm("fma.rn.f32x2 %0, %1, %2, %3;" : "=l"(d) : "l"(a), "l"(b), "l"(c));
    return d;
}
// HW tanh (MUFU.TANH)
__device__ __forceinline__ float tanh_fast(float x) {
    float y;
    asm("tanh.approx.f32 %0, %1;" : "=f"(y) : "f"(x));
    return y;
}
__device__ __forceinline__ float sigmoid_fast(float x) {
    return fmaf(0.5f, tanh_fast(0.5f * x), 0.5f);
}

// ---------------------------------------------------------------------------
// Prep: token->xgate table and packed Wh. Tiny.
// ---------------------------------------------------------------------------
__global__ void prep_kernel(const float* __restrict__ emb,
                            const float* __restrict__ Wx,
                            const float* __restrict__ b,
                            const float* __restrict__ Wh) {
    int tid = blockIdx.x * blockDim.x + threadIdx.x;
    if (tid < VOCAB * HID) {
        int v = tid / HID, j = tid % HID;
        float si = b[j], sf = b[HID + j], sg = b[2 * HID + j], so = b[3 * HID + j];
        #pragma unroll
        for (int e = 0; e < EMB; e++) {
            float xe = emb[v * EMB + e];
            si = fmaf(xe, Wx[e * 4 * HID + j], si);
            sf = fmaf(xe, Wx[e * 4 * HID + HID + j], sf);
            sg = fmaf(xe, Wx[e * 4 * HID + 2 * HID + j], sg);
            so = fmaf(xe, Wx[e * 4 * HID + 3 * HID + j], so);
        }
        g_tbl[tid] = make_float4(si, sf, sg, so);
    }
    if (tid < 4 * 16 * 32) {
        int j  = tid & 31;
        int k2 = (tid >> 5) & 15;
        int g  = tid >> 9;
        float w0 = Wh[(2 * k2) * 4 * HID + g * HID + j];
        float w1 = Wh[(2 * k2 + 1) * 4 * HID + g * HID + j];
        g_wpk[tid] = pack2(w0, w1);
    }
}

// ---------------------------------------------------------------------------
// Per-warp LSTM over CNT batch rows. Lane j owns hidden unit j of each row.
// h lives in ping-pong shared buffers, read per-use as broadcast LDS.128
// (ulonglong2 = two pre-packed f32x2 operands). Wh columns in registers.
// ---------------------------------------------------------------------------
template <int CNT>
__device__ __forceinline__ void lstm_rows(
    const int* __restrict__ x,
    const float* __restrict__ Wfc,
    const float* __restrict__ bfc,
    float* __restrict__ out,
    int rs, int lane,
    float (&hsm)[2][4][HID],
    const unsigned long long (&w)[64])
{
    const unsigned FULL = 0xffffffffu;

    #pragma unroll
    for (int r = 0; r < CNT; ++r) hsm[0][r][lane] = 0.f;
    __syncwarp();

    float c[CNT], hlast[CNT];
    #pragma unroll
    for (int r = 0; r < CNT; ++r) { c[r] = 0.f; hlast[r] = 0.f; }

    const int* xrow[CNT];
    #pragma unroll
    for (int r = 0; r < CNT; ++r) xrow[r] = x + (long long)(rs + r) * T_STEPS;

    for (int tc = 0; tc < T_STEPS / 32; ++tc) {
        int tokr[CNT];
        #pragma unroll
        for (int r = 0; r < CNT; ++r) tokr[r] = xrow[r][tc * 32 + lane];

        #pragma unroll 2
        for (int s = 0; s < 32; ++s) {
            const int buf = s & 1;

            // table loads first: LDG latency hides under the FMA loop
            float4 tb[CNT];
            #pragma unroll
            for (int r = 0; r < CNT; ++r) {
                int tok = __shfl_sync(FULL, tokr[r], s);
                tb[r] = __ldg(&g_tbl[tok * HID + lane]);
            }

            const ulonglong2* hp[CNT];
            #pragma unroll
            for (int r = 0; r < CNT; ++r)
                hp[r] = (const ulonglong2*)hsm[buf][r];

            unsigned long long acc[CNT][4];
            #pragma unroll
            for (int r = 0; r < CNT; ++r)
                acc[r][0] = acc[r][1] = acc[r][2] = acc[r][3] = 0ull;

            #pragma unroll
            for (int k4 = 0; k4 < 8; ++k4) {
                #pragma unroll
                for (int r = 0; r < CNT; ++r) {
                    ulonglong2 hq = hp[r][k4];       // one broadcast LDS.128
                    acc[r][0] = ffma2(hq.x, w[     2 * k4    ], acc[r][0]);
                    acc[r][0] = ffma2(hq.y, w[     2 * k4 + 1], acc[r][0]);
                    acc[r][1] = ffma2(hq.x, w[16 + 2 * k4    ], acc[r][1]);
                    acc[r][1] = ffma2(hq.y, w[16 + 2 * k4 + 1], acc[r][1]);
                    acc[r][2] = ffma2(hq.x, w[32 + 2 * k4    ], acc[r][2]);
                    acc[r][2] = ffma2(hq.y, w[32 + 2 * k4 + 1], acc[r][2]);
                    acc[r][3] = ffma2(hq.x, w[48 + 2 * k4    ], acc[r][3]);
                    acc[r][3] = ffma2(hq.y, w[48 + 2 * k4 + 1], acc[r][3]);
                }
            }

            #pragma unroll
            for (int r = 0; r < CNT; ++r) {
                float gi = tb[r].x + (lo2(acc[r][0]) + hi2(acc[r][0]));
                float gf = tb[r].y + (lo2(acc[r][1]) + hi2(acc[r][1]));
                float gg = tb[r].z + (lo2(acc[r][2]) + hi2(acc[r][2]));
                float go = tb[r].w + (lo2(acc[r][3]) + hi2(acc[r][3]));
                float is = sigmoid_fast(gi);
                float fs = sigmoid_fast(gf);
                float os = sigmoid_fast(go);
                float gt = tanh_fast(gg);
                c[r] = fmaf(fs, c[r], is * gt);
                float h = os * tanh_fast(c[r]);
                hlast[r] = h;
                hsm[buf ^ 1][r][lane] = h;       // write next-step buffer
            }
            __syncwarp();
        }
    }

    // FC head: out[b] = h @ W_fc + b_fc (warp butterfly reduce per row)
    float wf0 = Wfc[lane * 2 + 0], wf1 = Wfc[lane * 2 + 1];
    #pragma unroll
    for (int r = 0; r < CNT; ++r) {
        float u0 = hlast[r] * wf0;
        float u1 = hlast[r] * wf1;
        #pragma unroll
        for (int o = 16; o; o >>= 1) {
            u0 += __shfl_xor_sync(FULL, u0, o);
            u1 += __shfl_xor_sync(FULL, u1, o);
        }
        if (lane == 0) {
            out[(rs + r) * 2 + 0] = u0 + bfc[0];
            out[(rs + r) * 2 + 1] = u1 + bfc[1];
        }
    }
}

// ---------------------------------------------------------------------------
// Main: 148 blocks x 8 warps = 1184 warps; warp w owns rows
// [w*B/1184, (w+1)*B/1184) -> 3 or 4 rows each, perfectly balanced chip-wide.
// ---------------------------------------------------------------------------
__global__ void __launch_bounds__(NWARP * 32, 1)
lstm_kernel(const int* __restrict__ x,
            const float* __restrict__ Wfc,
            const float* __restrict__ bfc,
            float* __restrict__ out, int B, int totalWarps) {
    const int lane = threadIdx.x & 31;
    const int wid  = threadIdx.x >> 5;
    const int wglob = blockIdx.x * NWARP + wid;

    long long rs64 = (long long)wglob * B / totalWarps;
    long long re64 = (long long)(wglob + 1) * B / totalWarps;
    const int rs  = (int)rs64;
    const int cnt = (int)(re64 - rs64);
    if (cnt <= 0) return;

    // ping-pong h buffers: [warp][parity][row][unit]
    __shared__ __align__(16) float hsm[NWARP][2][4][HID];

    // 64 packed weight words (128 fp32), shared by all rows of this warp
    unsigned long long w[64];
    #pragma unroll
    for (int i = 0; i < 64; i++) w[i] = g_wpk[i * 32 + lane];

    switch (cnt) {
        case 4: lstm_rows<4>(x, Wfc, bfc, out, rs, lane, hsm[wid], w); break;
        case 3: lstm_rows<3>(x, Wfc, bfc, out, rs, lane, hsm[wid], w); break;
        case 2: lstm_rows<2>(x, Wfc, bfc, out, rs, lane, hsm[wid], w); break;
        default: lstm_rows<1>(x, Wfc, bfc, out, rs, lane, hsm[wid], w); break;
    }
}

// ---------------------------------------------------------------------------
// Harness entry
// Inputs: x[int32 B*T], emb[101*32], Wx[32*128], Wh[32*128], b[128],
//         W_fc[32*2], b_fc[2]. Output: float [B,2].
// ---------------------------------------------------------------------------
extern "C" void kernel_launch(void* const* d_in, const int* in_sizes, int n_in,
                              void* d_out, int out_size) {
    const int*   x   = (const int*)  d_in[0];
    const float* emb = (const float*)d_in[1];
    const float* Wx  = (const float*)d_in[2];
    const float* Wh  = (const float*)d_in[3];
    const float* b   = (const float*)d_in[4];
    const float* Wfc = (const float*)d_in[5];
    const float* bfc = (const float*)d_in[6];
    float* out = (float*)d_out;

    const int B = in_sizes[0] / T_STEPS;

    prep_kernel<<<(VOCAB * HID + 255) / 256, 256>>>(emb, Wx, b, Wh);

    int nblocks = 148;                               // one block per SM
    int minBlocks = (B + NWARP * 4 - 1) / (NWARP * 4);
    if (nblocks < minBlocks) nblocks = minBlocks;    // safety for larger B
    const int totalWarps = nblocks * NWARP;

    lstm_kernel<<<nblocks, NWARP * 32>>>(x, Wfc, bfc, out, B, totalWarps);
}